// round 3
// baseline (speedup 1.0000x reference)
#include <cuda_runtime.h>
#include <cstdint>

// Problem constants (from reference)
//   x: (B=4, D+C=105, FH=32, FW=88) fp32
//   out: (B=4, C=64, NZ=200, NX=200) fp32 = 10,240,000 elems
#define DD   41
#define CCH  64
#define FH_  32
#define FW_  88
#define B_   4
#define NX0_ 200
#define NZ_  200

// 3x3 inverse via adjugate with correctly-rounded divisions.
// Bit-identical to LAPACK LU for these matrices; __fdiv_rn guards against
// fast-math build flags. DO NOT change (bin-boundary sensitivity).
__device__ __forceinline__ void inv3(const float* m, float* o) {
    float a = m[0], b = m[1], c = m[2];
    float d = m[3], e = m[4], f = m[5];
    float g = m[6], h = m[7], i = m[8];
    float c00 = e * i - f * h;
    float c01 = f * g - d * i;
    float c02 = d * h - e * g;
    float det = a * c00 + b * c01 + c * c02;
    o[0] = __fdiv_rn(c00, det);
    o[1] = __fdiv_rn(c * h - b * i, det);
    o[2] = __fdiv_rn(b * f - c * e, det);
    o[3] = __fdiv_rn(c01, det);
    o[4] = __fdiv_rn(a * i - c * g, det);
    o[5] = __fdiv_rn(c * d - a * f, det);
    o[6] = __fdiv_rn(c02, det);
    o[7] = __fdiv_rn(b * g - a * h, det);
    o[8] = __fdiv_rn(a * e - b * d, det);
}

// ---------------------------------------------------------------------------
// Main kernel. One block per (w, b). 256 threads = 8 warps.
//  Phase 1: logits[41][32] -> smem; feature f[32] -> REGISTERS (coalesced,
//           loads in flight through phases 2-3)
//  Phase 2: softmax over D per pixel column h (8 partial groups)
//  Phase 3: per-(d,h) geometry -> bin + kept; h-uniformity check per d
//  Phase 4: warp wg: channel c = (wg&1)*32+lane, d-group dg = wg>>1:
//           v = sum_h wts[d][h]*f[h]; wts reads are warp-broadcast LDS,
//           f is registers. ONE atomic per (d, channel).
// ---------------------------------------------------------------------------
__global__ __launch_bounds__(256) void lss_main(
    const float* __restrict__ x,
    const float* __restrict__ intrins,
    const float* __restrict__ rots,
    const float* __restrict__ trans,
    float* __restrict__ out)
{
    __shared__ float wts[DD][FH_];      // logits -> exp -> masked weights
    __shared__ float pmax[8][FH_];
    __shared__ float psum[8][FH_];
    __shared__ float fullmax[FH_];
    __shared__ float fsum[FH_];
    __shared__ int   binsp[DD];
    __shared__ int   flags[DD];         // 0 = no kept, 1 = uniform, 2 = mixed
    __shared__ int   binh[DD][FH_];
    __shared__ float iR[9], iK[9], tv[3];

    const int w    = blockIdx.x;
    const int b    = blockIdx.y;
    const int tid  = threadIdx.x;
    const int lane = tid & 31;
    const int wg   = tid >> 5;           // 0..7
    const int c    = ((wg & 1) << 5) + lane;   // phase-4 channel
    const int dg   = wg >> 1;                  // phase-4 d-group (0..3)

    const float* xb = x + (size_t)b * (105 * FH_ * FW_) + w;

    // Phase 1a: logits 41x32 -> smem (scattered single-sector loads)
    for (int i = tid; i < DD * FH_; i += 256) {
        int d = i >> 5, h = i & 31;
        wts[d][h] = xb[(d * FH_ + h) * FW_];
    }

    // Phase 1b: feature column for this thread's channel -> registers.
    // Warp lanes hold consecutive c => each of the 32 loads is a coalesced
    // 128B warp transaction. Consumed only in phase 4 (latency hidden).
    float f[FH_];
    {
        const float* xf = xb + (size_t)(DD + c) * (FH_ * FW_);
#pragma unroll
        for (int h = 0; h < FH_; h++) f[h] = xf[h * FW_];
    }

    if (tid == 0) {
        float mr[9], mk[9];
#pragma unroll
        for (int k = 0; k < 9; k++) { mr[k] = rots[b * 9 + k]; mk[k] = intrins[b * 9 + k]; }
        inv3(mr, iR);
        inv3(mk, iK);
        tv[0] = trans[b * 3 + 0]; tv[1] = trans[b * 3 + 1]; tv[2] = trans[b * 3 + 2];
    }
    __syncthreads();

    // Phase 2: softmax over d per h. Group g (=wg) covers d = g, g+8, ...
    {
        float pm = -3.402823466e38f;
        for (int d = wg; d < DD; d += 8) pm = fmaxf(pm, wts[d][lane]);
        pmax[wg][lane] = pm;
    }
    __syncthreads();
    if (tid < 32) {
        float m = pmax[0][lane];
#pragma unroll
        for (int g = 1; g < 8; g++) m = fmaxf(m, pmax[g][lane]);
        fullmax[lane] = m;
    }
    __syncthreads();
    {
        float m = fullmax[lane];
        float ps = 0.f;
        for (int d = wg; d < DD; d += 8) {
            float e = __expf(wts[d][lane] - m);
            wts[d][lane] = e;
            ps += e;
        }
        psum[wg][lane] = ps;
    }
    __syncthreads();
    if (tid < 32) {
        float s = psum[0][lane];
#pragma unroll
        for (int g = 1; g < 8; g++) s += psum[g][lane];
        fsum[lane] = s;
    }
    __syncthreads();

    // Phase 3: geometry. warp wg handles d = wg, wg+8, ...; lane = h.
    {
        // frustum (replicating jnp.linspace: i * fl(step))
        const float xs = (float)w    * (703.0f / 87.0f);
        const float ys = (float)lane * (255.0f / 31.0f);
        const float r00 = iR[0], r01 = iR[1], r02 = iR[2];
        const float r10 = iR[3], r11 = iR[4], r12 = iR[5];
        const float r20 = iR[6], r21 = iR[7], r22 = iR[8];
        const float k00 = iK[0], k01 = iK[1], k02 = iK[2];
        const float k10 = iK[3], k11 = iK[4], k12 = iK[5];
        const float k20 = iK[6], k21 = iK[7], k22 = iK[8];
        const float t0 = tv[0], t1 = tv[1], t2 = tv[2];
        const float p0 = xs - t0, p1 = ys - t1;
        const float rinv = __frcp_rn(fsum[lane]);

        for (int d = wg; d < DD; d += 8) {
            float p2 = (4.0f + (float)d) - t2;
            // q = invR @ p
            float q0 = __fmaf_rn(r00, p0, __fmaf_rn(r01, p1, r02 * p2));
            float q1 = __fmaf_rn(r10, p0, __fmaf_rn(r11, p1, r12 * p2));
            float q2 = __fmaf_rn(r20, p0, __fmaf_rn(r21, p1, r22 * p2));
            // s = (qx*qz, qy*qz, qz)
            float s0 = q0 * q2, s1 = q1 * q2, s2 = q2;
            // g = invK @ s
            float g0 = __fmaf_rn(k00, s0, __fmaf_rn(k01, s1, k02 * s2));
            float g1 = __fmaf_rn(k10, s0, __fmaf_rn(k11, s1, k12 * s2));
            float g2 = __fmaf_rn(k20, s0, __fmaf_rn(k21, s1, k22 * s2));
            // coords: truncation toward zero matches astype(int32)
            int c0 = (int)((g0 + 50.0f) / 0.5f);
            int c1 = (int)((g1 + 10.0f) / 20.0f);
            int c2 = (int)(g2 / 0.25f);
            bool kept = (c0 >= 0) & (c0 < NX0_) & (c1 >= 0) & (c1 < 1) &
                        (c2 >= 0) & (c2 < NZ_);
            int sp = c2 * NX0_ + c0;
            binh[d][lane] = sp;
            float wv = kept ? wts[d][lane] * rinv : 0.0f;
            wts[d][lane] = wv;

            unsigned km = __ballot_sync(0xffffffffu, kept);
            int fl = 0;
            if (km) {
                int src = __ffs(km) - 1;
                int lsp = __shfl_sync(0xffffffffu, sp, src);
                bool ok = (!kept) || (sp == lsp);
                fl = __all_sync(0xffffffffu, ok) ? 1 : 2;
                if (lane == 0) binsp[d] = lsp;
            }
            if (lane == 0) flags[d] = fl;
        }
    }
    __syncthreads();

    // Phase 4: matvec + scatter. f[] in registers; wts reads are broadcasts.
    {
        float* ob = out + ((size_t)b * CCH + c) * (NZ_ * NX0_);
        for (int d = dg; d < DD; d += 4) {
            int fl = flags[d];
            if (fl == 0) continue;
            if (fl == 1) {
                float a0 = 0.f, a1 = 0.f, a2 = 0.f, a3 = 0.f;
#pragma unroll
                for (int h = 0; h < FH_; h += 4) {
                    a0 = __fmaf_rn(wts[d][h + 0], f[h + 0], a0);
                    a1 = __fmaf_rn(wts[d][h + 1], f[h + 1], a1);
                    a2 = __fmaf_rn(wts[d][h + 2], f[h + 2], a2);
                    a3 = __fmaf_rn(wts[d][h + 3], f[h + 3], a3);
                }
                atomicAdd(ob + binsp[d], (a0 + a1) + (a2 + a3));
            } else {
                // generic fallback: per-h scatter (fully unrolled so f[] stays
                // in registers)
#pragma unroll
                for (int h = 0; h < FH_; h++) {
                    float wv = wts[d][h];
                    if (wv != 0.f) atomicAdd(ob + binh[d][h], wv * f[h]);
                }
            }
        }
    }
}

// ---------------------------------------------------------------------------
extern "C" void kernel_launch(void* const* d_in, const int* in_sizes, int n_in,
                              void* d_out, int out_size) {
    const float* x       = (const float*)d_in[0];
    const float* intrins = (const float*)d_in[1];
    const float* rots    = (const float*)d_in[2];
    const float* trans   = (const float*)d_in[3];
    float* out = (float*)d_out;

    // zero the accumulator output (capturable memset node)
    cudaMemsetAsync(out, 0, (size_t)out_size * sizeof(float));

    dim3 grid(FW_, B_);
    lss_main<<<grid, 256>>>(x, intrins, rots, trans, out);
}

// round 4
// speedup vs baseline: 1.2206x; 1.2206x over previous
#include <cuda_runtime.h>
#include <cstdint>

// Problem constants (from reference)
//   x: (B=4, D+C=105, FH=32, FW=88) fp32
//   out: (B=4, C=64, NZ=200, NX=200) fp32 = 10,240,000 elems
#define DD   41
#define CCH  64
#define CHT  105          // DD + CCH
#define FH_  32
#define FW_  88
#define B_   4
#define NX0_ 200
#define NZ_  200
#define COLH (CHT * FH_)  // 3360 floats per (b,w) column in xT

// Static scratch: x transposed to [b][w][ch][h]  (4*88*3360*4B = 4.73 MB)
__device__ float g_xT[(size_t)B_ * FW_ * COLH];

// ---------------------------------------------------------------------------
// Kernel 1: transpose x[b][ch*32+h][w] -> xT[b][w][ch*32+h]
// Per b this is M[3360][88] -> MT[88][3360]; classic 32x32 smem tile.
// Both global sides fully coalesced.
// ---------------------------------------------------------------------------
__global__ __launch_bounds__(256) void lss_transpose(const float* __restrict__ x) {
    __shared__ float tile[32][33];
    const int b  = blockIdx.z;
    const int r0 = blockIdx.x * 32;   // row index = ch*32 + h  (0..3359)
    const int c0 = blockIdx.y * 32;   // col index = w          (0..87)
    const int tx = threadIdx.x;       // 0..31
    const int ty = threadIdx.y;       // 0..7

    const float* xb = x + (size_t)b * COLH * FW_;
#pragma unroll
    for (int i = ty; i < 32; i += 8) {
        int r = r0 + i, c = c0 + tx;
        if (c < FW_) tile[i][tx] = xb[(size_t)r * FW_ + c];   // r0+31 <= 3359 always
    }
    __syncthreads();
    float* xt = g_xT + (size_t)b * FW_ * COLH;
#pragma unroll
    for (int i = ty; i < 32; i += 8) {
        int w = c0 + i, r = r0 + tx;
        if (w < FW_) xt[(size_t)w * COLH + r] = tile[tx][i];
    }
}

// 3x3 inverse via adjugate with correctly-rounded divisions.
// Bit-identical to LAPACK LU for these matrices; __fdiv_rn guards against
// fast-math build flags. DO NOT change (bin-boundary sensitivity).
__device__ __forceinline__ void inv3(const float* m, float* o) {
    float a = m[0], b = m[1], c = m[2];
    float d = m[3], e = m[4], f = m[5];
    float g = m[6], h = m[7], i = m[8];
    float c00 = e * i - f * h;
    float c01 = f * g - d * i;
    float c02 = d * h - e * g;
    float det = a * c00 + b * c01 + c * c02;
    o[0] = __fdiv_rn(c00, det);
    o[1] = __fdiv_rn(c * h - b * i, det);
    o[2] = __fdiv_rn(b * f - c * e, det);
    o[3] = __fdiv_rn(c01, det);
    o[4] = __fdiv_rn(a * i - c * g, det);
    o[5] = __fdiv_rn(c * d - a * f, det);
    o[6] = __fdiv_rn(c02, det);
    o[7] = __fdiv_rn(b * g - a * h, det);
    o[8] = __fdiv_rn(a * e - b * d, det);
}

// ---------------------------------------------------------------------------
// Kernel 2: main. One block per (w, b). 256 threads = 8 warps.
// All global reads now hit the contiguous xT column for this (b,w).
// ---------------------------------------------------------------------------
__global__ __launch_bounds__(256) void lss_main(
    const float* __restrict__ intrins,
    const float* __restrict__ rots,
    const float* __restrict__ trans,
    float* __restrict__ out)
{
    __shared__ float wts[DD][FH_];      // logits -> exp -> masked weights
    __shared__ float pmax[8][FH_];
    __shared__ float psum[8][FH_];
    __shared__ float fullmax[FH_];
    __shared__ float fsum[FH_];
    __shared__ int   binsp[DD];
    __shared__ int   flags[DD];         // 0 = no kept, 1 = uniform, 2 = mixed
    __shared__ int   binh[DD][FH_];
    __shared__ float iR[9], iK[9], tv[3];

    const int w    = blockIdx.x;
    const int b    = blockIdx.y;
    const int tid  = threadIdx.x;
    const int lane = tid & 31;
    const int wg   = tid >> 5;                 // 0..7
    const int c    = ((wg & 1) << 5) + lane;   // phase-4 channel
    const int dg   = wg >> 1;                  // phase-4 d-group (0..3)

    const float* xt = g_xT + ((size_t)b * FW_ + w) * COLH;

    // Phase 1a: logits 41x32 (1312 floats, contiguous) -> smem via float4
    {
        const float4* src = (const float4*)xt;
        float4* dst = (float4*)&wts[0][0];
        for (int i = tid; i < (DD * FH_) / 4; i += 256) dst[i] = src[i];
    }

    // Phase 1b: feature row for this thread's channel -> registers.
    // xt[(DD+c)*32 .. +32) is 128B contiguous; warp lanes cover consecutive
    // 128B chunks => perfectly sequential. Consumed only in phase 4.
    float f[FH_];
    {
        const float4* xf = (const float4*)(xt + (size_t)(DD + c) * FH_);
#pragma unroll
        for (int k = 0; k < 8; k++) {
            float4 v = xf[k];
            f[4 * k + 0] = v.x; f[4 * k + 1] = v.y;
            f[4 * k + 2] = v.z; f[4 * k + 3] = v.w;
        }
    }

    if (tid == 0) {
        float mr[9], mk[9];
#pragma unroll
        for (int k = 0; k < 9; k++) { mr[k] = rots[b * 9 + k]; mk[k] = intrins[b * 9 + k]; }
        inv3(mr, iR);
        inv3(mk, iK);
        tv[0] = trans[b * 3 + 0]; tv[1] = trans[b * 3 + 1]; tv[2] = trans[b * 3 + 2];
    }
    __syncthreads();

    // Phase 2: softmax over d per h. Group g (=wg) covers d = g, g+8, ...
    {
        float pm = -3.402823466e38f;
        for (int d = wg; d < DD; d += 8) pm = fmaxf(pm, wts[d][lane]);
        pmax[wg][lane] = pm;
    }
    __syncthreads();
    if (tid < 32) {
        float m = pmax[0][lane];
#pragma unroll
        for (int g = 1; g < 8; g++) m = fmaxf(m, pmax[g][lane]);
        fullmax[lane] = m;
    }
    __syncthreads();
    {
        float m = fullmax[lane];
        float ps = 0.f;
        for (int d = wg; d < DD; d += 8) {
            float e = __expf(wts[d][lane] - m);
            wts[d][lane] = e;
            ps += e;
        }
        psum[wg][lane] = ps;
    }
    __syncthreads();
    if (tid < 32) {
        float s = psum[0][lane];
#pragma unroll
        for (int g = 1; g < 8; g++) s += psum[g][lane];
        fsum[lane] = s;
    }
    __syncthreads();

    // Phase 3: geometry. warp wg handles d = wg, wg+8, ...; lane = h.
    {
        // frustum (replicating jnp.linspace: i * fl(step))
        const float xs = (float)w    * (703.0f / 87.0f);
        const float ys = (float)lane * (255.0f / 31.0f);
        const float r00 = iR[0], r01 = iR[1], r02 = iR[2];
        const float r10 = iR[3], r11 = iR[4], r12 = iR[5];
        const float r20 = iR[6], r21 = iR[7], r22 = iR[8];
        const float k00 = iK[0], k01 = iK[1], k02 = iK[2];
        const float k10 = iK[3], k11 = iK[4], k12 = iK[5];
        const float k20 = iK[6], k21 = iK[7], k22 = iK[8];
        const float t0 = tv[0], t1 = tv[1], t2 = tv[2];
        const float p0 = xs - t0, p1 = ys - t1;
        const float rinv = __frcp_rn(fsum[lane]);

        for (int d = wg; d < DD; d += 8) {
            float p2 = (4.0f + (float)d) - t2;
            // q = invR @ p
            float q0 = __fmaf_rn(r00, p0, __fmaf_rn(r01, p1, r02 * p2));
            float q1 = __fmaf_rn(r10, p0, __fmaf_rn(r11, p1, r12 * p2));
            float q2 = __fmaf_rn(r20, p0, __fmaf_rn(r21, p1, r22 * p2));
            // s = (qx*qz, qy*qz, qz)
            float s0 = q0 * q2, s1 = q1 * q2, s2 = q2;
            // g = invK @ s
            float g0 = __fmaf_rn(k00, s0, __fmaf_rn(k01, s1, k02 * s2));
            float g1 = __fmaf_rn(k10, s0, __fmaf_rn(k11, s1, k12 * s2));
            float g2 = __fmaf_rn(k20, s0, __fmaf_rn(k21, s1, k22 * s2));
            // coords: truncation toward zero matches astype(int32)
            int c0 = (int)((g0 + 50.0f) / 0.5f);
            int c1 = (int)((g1 + 10.0f) / 20.0f);
            int c2 = (int)(g2 / 0.25f);
            bool kept = (c0 >= 0) & (c0 < NX0_) & (c1 >= 0) & (c1 < 1) &
                        (c2 >= 0) & (c2 < NZ_);
            int sp = c2 * NX0_ + c0;
            binh[d][lane] = sp;
            float wv = kept ? wts[d][lane] * rinv : 0.0f;
            wts[d][lane] = wv;

            unsigned km = __ballot_sync(0xffffffffu, kept);
            int fl = 0;
            if (km) {
                int src = __ffs(km) - 1;
                int lsp = __shfl_sync(0xffffffffu, sp, src);
                bool ok = (!kept) || (sp == lsp);
                fl = __all_sync(0xffffffffu, ok) ? 1 : 2;
                if (lane == 0) binsp[d] = lsp;
            }
            if (lane == 0) flags[d] = fl;
        }
    }
    __syncthreads();

    // Phase 4: matvec + scatter. f[] in registers; wts reads are broadcasts.
    {
        float* ob = out + ((size_t)b * CCH + c) * (NZ_ * NX0_);
        for (int d = dg; d < DD; d += 4) {
            int fl = flags[d];
            if (fl == 0) continue;
            if (fl == 1) {
                float a0 = 0.f, a1 = 0.f, a2 = 0.f, a3 = 0.f;
#pragma unroll
                for (int h = 0; h < FH_; h += 4) {
                    a0 = __fmaf_rn(wts[d][h + 0], f[h + 0], a0);
                    a1 = __fmaf_rn(wts[d][h + 1], f[h + 1], a1);
                    a2 = __fmaf_rn(wts[d][h + 2], f[h + 2], a2);
                    a3 = __fmaf_rn(wts[d][h + 3], f[h + 3], a3);
                }
                atomicAdd(ob + binsp[d], (a0 + a1) + (a2 + a3));
            } else {
                // generic fallback: per-h scatter (unrolled so f[] stays in regs)
#pragma unroll
                for (int h = 0; h < FH_; h++) {
                    float wv = wts[d][h];
                    if (wv != 0.f) atomicAdd(ob + binh[d][h], wv * f[h]);
                }
            }
        }
    }
}

// ---------------------------------------------------------------------------
extern "C" void kernel_launch(void* const* d_in, const int* in_sizes, int n_in,
                              void* d_out, int out_size) {
    const float* x       = (const float*)d_in[0];
    const float* intrins = (const float*)d_in[1];
    const float* rots    = (const float*)d_in[2];
    const float* trans   = (const float*)d_in[3];
    float* out = (float*)d_out;

    // zero the accumulator output (capturable memset node)
    cudaMemsetAsync(out, 0, (size_t)out_size * sizeof(float));

    // transpose x into [b][w][ch][h] scratch (coalesced both sides)
    dim3 tgrid(COLH / 32, (FW_ + 31) / 32, B_);
    lss_transpose<<<tgrid, dim3(32, 8)>>>(x);

    dim3 grid(FW_, B_);
    lss_main<<<grid, 256>>>(intrins, rots, trans, out);
}